// round 6
// baseline (speedup 1.0000x reference)
#include <cuda_runtime.h>
#include <cstdint>

constexpr int CN = 384;
constexpr int NHEAD = 4;
constexpr int HDIM = 96;
constexpr int HH = 64;
constexpr int WW = 128;
constexpr int HW = HH * WW;   // 8192
constexpr int BB = 8;

// Scratch (device globals: allocation-free, harness-legal)
__device__ float g_q[BB * CN * HW];
__device__ float g_kv[BB * 2 * CN * HW];
__device__ float g_ao[BB * CN * HW];
__device__ float g_o2[BB * CN * HW];
__device__ float g_psum[BB * CN];
__device__ float g_psq[BB * CN];
__device__ float g_scale[CN];
__device__ float g_shift[CN];

__device__ __forceinline__ float to_tf32(float x) {
    uint32_t u;
    asm("cvt.rna.tf32.f32 %0, %1;" : "=r"(u) : "f"(x));
    return __uint_as_float(u);
}
__device__ __forceinline__ void mma_tf32(float4& d, const uint32_t a[4], const uint32_t b[2]) {
    asm volatile(
        "mma.sync.aligned.m16n8k8.row.col.f32.tf32.tf32.f32 "
        "{%0,%1,%2,%3}, {%4,%5,%6,%7}, {%8,%9}, {%0,%1,%2,%3};\n"
        : "+f"(d.x), "+f"(d.y), "+f"(d.z), "+f"(d.w)
        : "r"(a[0]), "r"(a[1]), "r"(a[2]), "r"(a[3]), "r"(b[0]), "r"(b[1]));
}
__device__ __forceinline__ uint32_t smem_u32(const void* p) {
    uint32_t a;
    asm("{ .reg .u64 t; cvta.to.shared.u64 t, %1; cvt.u32.u64 %0, t; }" : "=r"(a) : "l"(p));
    return a;
}
__device__ __forceinline__ void cp16(uint32_t d, const void* g) {
    asm volatile("cp.async.cg.shared.global [%0], [%1], 16;" :: "r"(d), "l"(g));
}

// ===========================================================================
// Projection GEMM: tf32 mma + 3-stage cp.async pipeline (2 tiles in flight).
// Block tile 128(M) x 256(N), K-tile 32. 256 threads = 8 warps at 64x64.
//   Y[(bz*M + m)*HW + n] = epi( sum_c A[m][c] * X[(bz*Cin + c)*HW + n] + bias[m] )
// A rows split (A0|A1) at Msplit; X channels split (X0|X1) at Ksplit.
// MODE 0: plain store. MODE 1: gate epilogue  Y = fs + sigmoid(v) * o2.
// ===========================================================================
constexpr int APADP = 36;                  // A row stride (floats)
constexpr int BPADP = 264;                 // B row stride (floats)
constexpr int ASTGP = 128 * APADP;         // 4608 floats
constexpr int BSTGP = 32 * BPADP;          // 8448 floats
constexpr int STGP = ASTGP + BSTGP;        // 13056 floats / stage
constexpr int GSMEMP = 3 * STGP * 4;       // 156,672 B

template <int MODE>
__global__ __launch_bounds__(256, 1)
void gemm_p(const float* __restrict__ A0, const float* __restrict__ A1,
            int Msplit, int lda,
            const float* __restrict__ bias0, const float* __restrict__ bias1,
            const float* __restrict__ X0, const float* __restrict__ X1,
            int Ksplit, int M, int K,
            float* __restrict__ Y,
            const float* __restrict__ fs, const float* __restrict__ o2)
{
    extern __shared__ float smf[];
    const uint32_t sb = smem_u32(smf);
    const int tid = threadIdx.x;
    const int lane = tid & 31;
    const int warp = tid >> 5;
    const int group = lane >> 2;
    const int tig = lane & 3;
    const int wm = warp & 1;
    const int wn = warp >> 1;
    const int row0 = blockIdx.x * 128;
    const int col0 = blockIdx.y * 256;
    const int bz = blockIdx.z;
    const int C1 = K - Ksplit;
    const int KT = K >> 5;   // k-tiles of 32

    // loader maps (256 threads)
    const int arow_i = tid >> 1;                 // A row 0..127
    const int ahalf = (tid & 1) * 16;            // 16-float half of 32
    const int mg = row0 + arow_i;
    const float* aptr = (mg < Msplit) ? (A0 + (size_t)mg * lda)
                                      : (A1 + (size_t)(mg - Msplit) * lda);
    const int brow = tid >> 3;                   // B k-row 0..31
    const int bcol = (tid & 7) * 32;             // 32-float chunk of 256

    auto xrow = [&](int cg) -> const float* {
        return (cg < Ksplit) ? (X0 + ((size_t)bz * Ksplit + cg) * HW)
                             : (X1 + ((size_t)bz * C1 + (cg - Ksplit)) * HW);
    };

    auto load_tile = [&](int kt) {
        const uint32_t base = sb + (kt % 3) * (STGP * 4);
        const float* ag = aptr + kt * 32 + ahalf;
        const uint32_t adst = base + (arow_i * APADP + ahalf) * 4;
#pragma unroll
        for (int j = 0; j < 4; j++) cp16(adst + j * 16, ag + j * 4);
        const float* bg = xrow(kt * 32 + brow) + col0 + bcol;
        const uint32_t bdst = base + (ASTGP + brow * BPADP + bcol) * 4;
#pragma unroll
        for (int j = 0; j < 8; j++) cp16(bdst + j * 16, bg + j * 4);
        asm volatile("cp.async.commit_group;" ::: "memory");
    };

    float4 acc[4][8];
#pragma unroll
    for (int i = 0; i < 4; i++)
#pragma unroll
        for (int j = 0; j < 8; j++) acc[i][j] = make_float4(0.f, 0.f, 0.f, 0.f);

    load_tile(0);
    load_tile(1);

    for (int kt = 0; kt < KT; kt++) {
        if (kt + 1 < KT) asm volatile("cp.async.wait_group 1;" ::: "memory");
        else             asm volatile("cp.async.wait_group 0;" ::: "memory");
        __syncthreads();
        if (kt + 2 < KT) load_tile(kt + 2);

        const float* Ab = smf + (kt % 3) * STGP;
        const float* Bb = Ab + ASTGP;
#pragma unroll
        for (int kk = 0; kk < 32; kk += 8) {
            uint32_t a[4][4], b[8][2];
#pragma unroll
            for (int mt = 0; mt < 4; mt++) {
                const int r = wm * 64 + mt * 16 + group;
                a[mt][0] = __float_as_uint(Ab[r * APADP + kk + tig]);
                a[mt][1] = __float_as_uint(Ab[(r + 8) * APADP + kk + tig]);
                a[mt][2] = __float_as_uint(Ab[r * APADP + kk + tig + 4]);
                a[mt][3] = __float_as_uint(Ab[(r + 8) * APADP + kk + tig + 4]);
            }
#pragma unroll
            for (int nt = 0; nt < 8; nt++) {
                const int c = wn * 64 + nt * 8 + group;
                b[nt][0] = __float_as_uint(Bb[(kk + tig) * BPADP + c]);
                b[nt][1] = __float_as_uint(Bb[(kk + tig + 4) * BPADP + c]);
            }
#pragma unroll
            for (int mt = 0; mt < 4; mt++)
#pragma unroll
                for (int nt = 0; nt < 8; nt++)
                    mma_tf32(acc[mt][nt], a[mt], b[nt]);
        }
        __syncthreads();
    }

    // ---- epilogue ----
#pragma unroll
    for (int mt = 0; mt < 4; mt++) {
        const int r0 = row0 + wm * 64 + mt * 16 + group;
        const int r1 = r0 + 8;
        const float bia0 = (r0 < Msplit) ? bias0[r0] : bias1[r0 - Msplit];
        const float bia1 = (r1 < Msplit) ? bias0[r1] : bias1[r1 - Msplit];
#pragma unroll
        for (int nt = 0; nt < 8; nt++) {
            const int n = col0 + wn * 64 + nt * 8 + tig * 2;
            const size_t i0 = ((size_t)bz * M + r0) * HW + n;
            const size_t i1 = ((size_t)bz * M + r1) * HW + n;
            const float4 c = acc[mt][nt];
            if (MODE == 0) {
                *(float2*)(Y + i0) = make_float2(c.x + bia0, c.y + bia0);
                *(float2*)(Y + i1) = make_float2(c.z + bia1, c.w + bia1);
            } else {
                const float2 f0 = *(const float2*)(fs + i0);
                const float2 f1 = *(const float2*)(fs + i1);
                const float2 q0 = *(const float2*)(o2 + i0);
                const float2 q1 = *(const float2*)(o2 + i1);
                float v; float2 r;
                v = c.x + bia0; r.x = f0.x + q0.x / (1.f + __expf(-v));
                v = c.y + bia0; r.y = f0.y + q0.y / (1.f + __expf(-v));
                *(float2*)(Y + i0) = r;
                v = c.z + bia1; r.x = f1.x + q1.x / (1.f + __expf(-v));
                v = c.w + bia1; r.y = f1.y + q1.y / (1.f + __expf(-v));
                *(float2*)(Y + i1) = r;
            }
        }
    }
}

// ===========================================================================
// Epipolar attention (tf32 legacy mma, round-3 proven). One block per (h,n,b).
// ===========================================================================
constexpr int SP = 136;
constexpr int ATT_SMEM = (HDIM + HDIM + WW) * SP * 4;  // 174,080 B

__global__ __launch_bounds__(256, 1)
void attn_k(const float* __restrict__ q, const float* __restrict__ kv,
            float* __restrict__ ao)
{
    extern __shared__ float sm[];
    float* Qs = sm;
    float* Ks = sm + HDIM * SP;
    float* Ss = sm + 2 * HDIM * SP;
    const int h = blockIdx.x, n = blockIdx.y, b = blockIdx.z;
    const int tid = threadIdx.x;
    const int lane = tid & 31;
    const int warp = tid >> 5;
    const int group = lane >> 2;
    const int tig = lane & 3;

    const size_t qbase = (((size_t)b * CN + n * HDIM) * HH + h) * WW;
    const size_t kbase = (((size_t)b * 2 * CN + n * HDIM) * HH + h) * WW;
    const size_t vbase = kbase + (size_t)CN * HW;

    {
        const int l4 = lane * 4;
#pragma unroll
        for (int it = 0; it < 12; it++) {
            const int cc = warp + it * 8;
            float4 a = *(const float4*)(q + qbase + (size_t)cc * HW + l4);
            float4 c = *(const float4*)(kv + kbase + (size_t)cc * HW + l4);
            *(float4*)&Qs[cc * SP + l4] =
                make_float4(to_tf32(a.x), to_tf32(a.y), to_tf32(a.z), to_tf32(a.w));
            *(float4*)&Ks[cc * SP + l4] =
                make_float4(to_tf32(c.x), to_tf32(c.y), to_tf32(c.z), to_tf32(c.w));
        }
    }
    __syncthreads();

    {   // GEMM1: S[wp][w] = scale * sum_cc K[cc][wp] * Q[cc][w]
        const int wm = warp & 1, wn = warp >> 1;
        float4 acc[4][4];
#pragma unroll
        for (int i = 0; i < 4; i++)
#pragma unroll
            for (int j = 0; j < 4; j++) acc[i][j] = make_float4(0.f, 0.f, 0.f, 0.f);
#pragma unroll
        for (int kk = 0; kk < HDIM; kk += 8) {
            uint32_t a[4][4], bfr[4][2];
#pragma unroll
            for (int mt = 0; mt < 4; mt++) {
                const int wp = wm * 64 + mt * 16 + group;
                a[mt][0] = __float_as_uint(Ks[(kk + tig) * SP + wp]);
                a[mt][1] = __float_as_uint(Ks[(kk + tig) * SP + wp + 8]);
                a[mt][2] = __float_as_uint(Ks[(kk + tig + 4) * SP + wp]);
                a[mt][3] = __float_as_uint(Ks[(kk + tig + 4) * SP + wp + 8]);
            }
#pragma unroll
            for (int nt = 0; nt < 4; nt++) {
                const int w = wn * 32 + nt * 8 + group;
                bfr[nt][0] = __float_as_uint(Qs[(kk + tig) * SP + w]);
                bfr[nt][1] = __float_as_uint(Qs[(kk + tig + 4) * SP + w]);
            }
#pragma unroll
            for (int mt = 0; mt < 4; mt++)
#pragma unroll
                for (int nt = 0; nt < 4; nt++)
                    mma_tf32(acc[mt][nt], a[mt], bfr[nt]);
        }
        const float scale = 0.10206207261596575f;
#pragma unroll
        for (int mt = 0; mt < 4; mt++) {
            const int wp = wm * 64 + mt * 16 + group;
#pragma unroll
            for (int nt = 0; nt < 4; nt++) {
                const int w = wn * 32 + nt * 8 + tig * 2;
                const float4 c = acc[mt][nt];
                *(float2*)&Ss[wp * SP + w] = make_float2(c.x * scale, c.y * scale);
                *(float2*)&Ss[(wp + 8) * SP + w] = make_float2(c.z * scale, c.w * scale);
            }
        }
    }
    __syncthreads();

    if (tid < WW) {
        const int w = tid;
        float mx = -1e30f;
#pragma unroll 8
        for (int wp = 0; wp < WW; wp++) mx = fmaxf(mx, Ss[wp * SP + w]);
        float s = 0.f;
#pragma unroll 8
        for (int wp = 0; wp < WW; wp++) {
            const float e = __expf(Ss[wp * SP + w] - mx);
            Ss[wp * SP + w] = e;
            s += e;
        }
        const float inv = 1.f / s;
#pragma unroll 8
        for (int wp = 0; wp < WW; wp++) Ss[wp * SP + w] = to_tf32(Ss[wp * SP + w] * inv);
    } else {
        const int t = tid - 128;
        const int l4 = (t & 31) * 4;
        const int r0 = t >> 5;
#pragma unroll
        for (int it = 0; it < 24; it++) {
            const int cc = r0 + it * 4;
            float4 c = *(const float4*)(kv + vbase + (size_t)cc * HW + l4);
            *(float4*)&Ks[cc * SP + l4] =
                make_float4(to_tf32(c.x), to_tf32(c.y), to_tf32(c.z), to_tf32(c.w));
        }
    }
    __syncthreads();

    if (warp < 6) {
        const int m0 = warp * 16;
        float4 acc[16];
#pragma unroll
        for (int j = 0; j < 16; j++) acc[j] = make_float4(0.f, 0.f, 0.f, 0.f);
#pragma unroll 4
        for (int kk = 0; kk < WW; kk += 8) {
            uint32_t a[4], bfr[16][2];
            a[0] = __float_as_uint(Ks[(m0 + group) * SP + kk + tig]);
            a[1] = __float_as_uint(Ks[(m0 + group + 8) * SP + kk + tig]);
            a[2] = __float_as_uint(Ks[(m0 + group) * SP + kk + tig + 4]);
            a[3] = __float_as_uint(Ks[(m0 + group + 8) * SP + kk + tig + 4]);
#pragma unroll
            for (int nt = 0; nt < 16; nt++) {
                const int w = nt * 8 + group;
                bfr[nt][0] = __float_as_uint(Ss[(kk + tig) * SP + w]);
                bfr[nt][1] = __float_as_uint(Ss[(kk + tig + 4) * SP + w]);
            }
#pragma unroll
            for (int nt = 0; nt < 16; nt++)
                mma_tf32(acc[nt], a, bfr[nt]);
        }
#pragma unroll
        for (int nt = 0; nt < 16; nt++) {
            const int w = nt * 8 + tig * 2;
            const float4 c = acc[nt];
            *(float2*)(ao + qbase + (size_t)(m0 + group) * HW + w) = make_float2(c.x, c.y);
            *(float2*)(ao + qbase + (size_t)(m0 + group + 8) * HW + w) = make_float2(c.z, c.w);
        }
    }
}

// ===========================================================================
// BatchNorm (training-mode batch stats), 3 stages, no atomics
// ===========================================================================
__global__ __launch_bounds__(256)
void bnstats_k(const float* __restrict__ y)
{
    const int bc = blockIdx.x;
    const float4* p = (const float4*)(y + (size_t)bc * HW);
    const int tid = threadIdx.x;
    float s = 0.f, sq = 0.f;
#pragma unroll
    for (int it = 0; it < 8; it++) {
        const float4 v = p[tid + it * 256];
        s += v.x + v.y + v.z + v.w;
        sq += v.x * v.x + v.y * v.y + v.z * v.z + v.w * v.w;
    }
#pragma unroll
    for (int o = 16; o > 0; o >>= 1) {
        s += __shfl_down_sync(0xffffffffu, s, o);
        sq += __shfl_down_sync(0xffffffffu, sq, o);
    }
    __shared__ float ss[8], sqq[8];
    if ((tid & 31) == 0) { ss[tid >> 5] = s; sqq[tid >> 5] = sq; }
    __syncthreads();
    if (tid == 0) {
        float ts = 0.f, tq = 0.f;
#pragma unroll
        for (int i = 0; i < 8; i++) { ts += ss[i]; tq += sqq[i]; }
        g_psum[bc] = ts;
        g_psq[bc] = tq;
    }
}

__global__ void bnfin_k(const float* __restrict__ gamma,
                        const float* __restrict__ beta)
{
    const int c = threadIdx.x;
    float s = 0.f, sq = 0.f;
#pragma unroll
    for (int b = 0; b < BB; b++) { s += g_psum[b * CN + c]; sq += g_psq[b * CN + c]; }
    const float invN = 1.f / (float)(BB * HW);
    const float mean = s * invN;
    const float var = sq * invN - mean * mean;
    const float inv = rsqrtf(var + 1e-5f);
    const float sc = gamma[c] * inv;
    g_scale[c] = sc;
    g_shift[c] = beta[c] - mean * sc;
}

__global__ void bnapply_k(float* __restrict__ y)
{
    const size_t i = ((size_t)blockIdx.x * 256 + threadIdx.x) * 4;
    const int c = (int)((i >> 13) % CN);
    float4 v = *(float4*)(y + i);
    const float sc = g_scale[c], sh = g_shift[c];
    v.x = v.x * sc + sh;
    v.y = v.y * sc + sh;
    v.z = v.z * sc + sh;
    v.w = v.w * sc + sh;
    *(float4*)(y + i) = v;
}

// ===========================================================================
extern "C" void kernel_launch(void* const* d_in, const int* in_sizes, int n_in,
                              void* d_out, int out_size)
{
    (void)in_sizes; (void)n_in; (void)out_size;
    const float* fs    = (const float*)d_in[0];
    const float* fo    = (const float*)d_in[1];
    const float* wq    = (const float*)d_in[2];
    const float* bq    = (const float*)d_in[3];
    const float* wk    = (const float*)d_in[4];
    const float* bk    = (const float*)d_in[5];
    const float* wv    = (const float*)d_in[6];
    const float* bv    = (const float*)d_in[7];
    const float* wo    = (const float*)d_in[8];
    const float* bo    = (const float*)d_in[9];
    const float* wg    = (const float*)d_in[10];
    const float* bg    = (const float*)d_in[11];
    const float* gamma = (const float*)d_in[12];
    const float* beta  = (const float*)d_in[13];
    float* out = (float*)d_out;

    float *q, *kvb, *ao, *o2;
    cudaGetSymbolAddress((void**)&q,   g_q);
    cudaGetSymbolAddress((void**)&kvb, g_kv);
    cudaGetSymbolAddress((void**)&ao,  g_ao);
    cudaGetSymbolAddress((void**)&o2,  g_o2);

    cudaFuncSetAttribute(gemm_p<0>, cudaFuncAttributeMaxDynamicSharedMemorySize, GSMEMP);
    cudaFuncSetAttribute(gemm_p<1>, cudaFuncAttributeMaxDynamicSharedMemorySize, GSMEMP);
    cudaFuncSetAttribute(attn_k, cudaFuncAttributeMaxDynamicSharedMemorySize, ATT_SMEM);

    // Q = wq @ feat_self + bq
    gemm_p<0><<<dim3(3, 32, 8), 256, GSMEMP>>>(wq, wq, CN, CN, bq, bq,
                                               fs, fs, CN, CN, CN, q, nullptr, nullptr);
    // [K;V] = [wk;wv] @ feat_other + [bk;bv]
    gemm_p<0><<<dim3(6, 32, 8), 256, GSMEMP>>>(wk, wv, CN, CN, bk, bv,
                                               fo, fo, CN, 2 * CN, CN, kvb, nullptr, nullptr);
    // attention
    attn_k<<<dim3(HH, NHEAD, BB), 256, ATT_SMEM>>>(q, kvb, ao);
    // out2 = wo @ attn_out + bo
    gemm_p<0><<<dim3(3, 32, 8), 256, GSMEMP>>>(wo, wo, CN, CN, bo, bo,
                                               ao, ao, CN, CN, CN, o2, nullptr, nullptr);
    // fused = fs + sigmoid(wg @ [fs; out2] + bg) * out2  -> d_out
    gemm_p<1><<<dim3(3, 32, 8), 256, GSMEMP>>>(wg, wg, CN, 2 * CN, bg, bg,
                                               fs, o2, CN, CN, 2 * CN, out, fs, o2);
    // BatchNorm
    bnstats_k<<<BB * CN, 256>>>(out);
    bnfin_k<<<1, CN>>>(gamma, beta);
    bnapply_k<<<BB * CN * HW / 1024, 256>>>(out);
}

// round 10
// speedup vs baseline: 1.0957x; 1.0957x over previous
#include <cuda_runtime.h>
#include <cstdint>

constexpr int CN = 384;
constexpr int NHEAD = 4;
constexpr int HDIM = 96;
constexpr int HH = 64;
constexpr int WW = 128;
constexpr int HW = HH * WW;   // 8192
constexpr int BB = 8;

// Scratch (device globals: allocation-free, harness-legal)
__device__ float g_q[BB * CN * HW];
__device__ float g_kv[BB * 2 * CN * HW];
__device__ float g_ao[BB * CN * HW];
__device__ float g_o2[BB * CN * HW];
__device__ float g_psum[BB * CN];
__device__ float g_psq[BB * CN];
__device__ float g_scale[CN];
__device__ float g_shift[CN];

__device__ __forceinline__ float to_tf32(float x) {
    uint32_t u;
    asm("cvt.rna.tf32.f32 %0, %1;" : "=r"(u) : "f"(x));
    return __uint_as_float(u);
}
__device__ __forceinline__ void mma_tf32(float4& d, const uint32_t a[4], const uint32_t b[2]) {
    asm volatile(
        "mma.sync.aligned.m16n8k8.row.col.f32.tf32.tf32.f32 "
        "{%0,%1,%2,%3}, {%4,%5,%6,%7}, {%8,%9}, {%0,%1,%2,%3};\n"
        : "+f"(d.x), "+f"(d.y), "+f"(d.z), "+f"(d.w)
        : "r"(a[0]), "r"(a[1]), "r"(a[2]), "r"(a[3]), "r"(b[0]), "r"(b[1]));
}
__device__ __forceinline__ uint32_t smem_u32(const void* p) {
    uint32_t a;
    asm("{ .reg .u64 t; cvta.to.shared.u64 t, %1; cvt.u32.u64 %0, t; }" : "=r"(a) : "l"(p));
    return a;
}
__device__ __forceinline__ void cp16(uint32_t d, const void* g) {
    asm volatile("cp.async.cg.shared.global [%0], [%1], 16;" :: "r"(d), "l"(g));
}

// ===========================================================================
// Projection GEMM (R3-proven): tf32 mma, block 128(M) x 256(N), K-tile 16,
// 8 warps at 64x64, register-prefetch double buffer (weights stay L1-hot).
// MODE 0: plain store. MODE 1: gate epilogue + fused BN-stats accumulation.
// ===========================================================================
constexpr int APAD = 20;
constexpr int BPAD = 264;
constexpr int ASZ = 128 * APAD;
constexpr int BSZ = 16 * BPAD;
constexpr int GSMEM = (2 * ASZ + 2 * BSZ) * 4;   // 54,272 B

template <int MODE>
__global__ __launch_bounds__(256, 1)
void gemm_t(const float* __restrict__ A0, const float* __restrict__ A1,
            int Msplit, int lda,
            const float* __restrict__ bias0, const float* __restrict__ bias1,
            const float* __restrict__ X0, const float* __restrict__ X1,
            int Ksplit, int M, int K,
            float* __restrict__ Y,
            const float* __restrict__ fs, const float* __restrict__ o2)
{
    extern __shared__ float smg[];
    float* Asb = smg;
    float* Bsb = smg + 2 * ASZ;

    const int tid = threadIdx.x;
    const int lane = tid & 31;
    const int warp = tid >> 5;
    const int group = lane >> 2;
    const int tig = lane & 3;
    const int wm = warp & 1;
    const int wn = warp >> 1;
    const int row0 = blockIdx.y * 128;
    const int col0 = blockIdx.x * 256;
    const int bz = blockIdx.z;
    const int C1 = K - Ksplit;

    const int m_ld = tid >> 1;
    const int kq = (tid & 1) * 8;
    const int mg = row0 + m_ld;
    const float* aptr = (mg < Msplit) ? (A0 + (size_t)mg * lda)
                                      : (A1 + (size_t)(mg - Msplit) * lda);
    const int kb = tid >> 6;
    const int nq4 = (tid & 63) * 4;

    float4 acc[4][8];
#pragma unroll
    for (int i = 0; i < 4; i++)
#pragma unroll
        for (int j = 0; j < 8; j++) acc[i][j] = make_float4(0.f, 0.f, 0.f, 0.f);

    const int iters = K >> 4;

    auto xrow = [&](int cg) -> const float* {
        return (cg < Ksplit) ? (X0 + ((size_t)bz * Ksplit + cg) * HW)
                             : (X1 + ((size_t)bz * C1 + (cg - Ksplit)) * HW);
    };

    {   // prologue: tile 0 into buffer 0
        float4 a0 = *(const float4*)(aptr + kq);
        float4 a1 = *(const float4*)(aptr + kq + 4);
        *(float4*)&Asb[m_ld * APAD + kq] =
            make_float4(to_tf32(a0.x), to_tf32(a0.y), to_tf32(a0.z), to_tf32(a0.w));
        *(float4*)&Asb[m_ld * APAD + kq + 4] =
            make_float4(to_tf32(a1.x), to_tf32(a1.y), to_tf32(a1.z), to_tf32(a1.w));
#pragma unroll
        for (int j = 0; j < 4; j++) {
            const int kr = kb + 4 * j;
            float4 b = *(const float4*)(xrow(kr) + col0 + nq4);
            *(float4*)&Bsb[kr * BPAD + nq4] =
                make_float4(to_tf32(b.x), to_tf32(b.y), to_tf32(b.z), to_tf32(b.w));
        }
    }
    __syncthreads();

    for (int it = 0; it < iters; it++) {
        const int buf = it & 1;
        float4 pa0, pa1, pb[4];
        const bool more = (it + 1 < iters);
        if (more) {
            const int k0 = (it + 1) << 4;
            pa0 = *(const float4*)(aptr + k0 + kq);
            pa1 = *(const float4*)(aptr + k0 + kq + 4);
#pragma unroll
            for (int j = 0; j < 4; j++)
                pb[j] = *(const float4*)(xrow(k0 + kb + 4 * j) + col0 + nq4);
        }

        const float* Ab = Asb + buf * ASZ;
        const float* Bb = Bsb + buf * BSZ;

        // ---- kk = 0 block ----
        {
            uint32_t a[4][4], b[8][2];
#pragma unroll
            for (int mt = 0; mt < 4; mt++) {
                const int r = wm * 64 + mt * 16 + group;
                a[mt][0] = __float_as_uint(Ab[r * APAD + tig]);
                a[mt][1] = __float_as_uint(Ab[(r + 8) * APAD + tig]);
                a[mt][2] = __float_as_uint(Ab[r * APAD + tig + 4]);
                a[mt][3] = __float_as_uint(Ab[(r + 8) * APAD + tig + 4]);
            }
#pragma unroll
            for (int nt = 0; nt < 8; nt++) {
                const int c = wn * 64 + nt * 8 + group;
                b[nt][0] = __float_as_uint(Bb[tig * BPAD + c]);
                b[nt][1] = __float_as_uint(Bb[(tig + 4) * BPAD + c]);
            }
#pragma unroll
            for (int mt = 0; mt < 4; mt++)
#pragma unroll
                for (int nt = 0; nt < 8; nt++)
                    mma_tf32(acc[mt][nt], a[mt], b[nt]);
        }

        // store prefetched tile (overlaps with kk=8 compute below)
        if (more) {
            float* An = Asb + (buf ^ 1) * ASZ;
            float* Bn = Bsb + (buf ^ 1) * BSZ;
            *(float4*)&An[m_ld * APAD + kq] =
                make_float4(to_tf32(pa0.x), to_tf32(pa0.y), to_tf32(pa0.z), to_tf32(pa0.w));
            *(float4*)&An[m_ld * APAD + kq + 4] =
                make_float4(to_tf32(pa1.x), to_tf32(pa1.y), to_tf32(pa1.z), to_tf32(pa1.w));
#pragma unroll
            for (int j = 0; j < 4; j++) {
                const int kr = kb + 4 * j;
                *(float4*)&Bn[kr * BPAD + nq4] =
                    make_float4(to_tf32(pb[j].x), to_tf32(pb[j].y), to_tf32(pb[j].z), to_tf32(pb[j].w));
            }
        }

        // ---- kk = 8 block ----
        {
            uint32_t a[4][4], b[8][2];
#pragma unroll
            for (int mt = 0; mt < 4; mt++) {
                const int r = wm * 64 + mt * 16 + group;
                a[mt][0] = __float_as_uint(Ab[r * APAD + 8 + tig]);
                a[mt][1] = __float_as_uint(Ab[(r + 8) * APAD + 8 + tig]);
                a[mt][2] = __float_as_uint(Ab[r * APAD + 8 + tig + 4]);
                a[mt][3] = __float_as_uint(Ab[(r + 8) * APAD + 8 + tig + 4]);
            }
#pragma unroll
            for (int nt = 0; nt < 8; nt++) {
                const int c = wn * 64 + nt * 8 + group;
                b[nt][0] = __float_as_uint(Bb[(8 + tig) * BPAD + c]);
                b[nt][1] = __float_as_uint(Bb[(8 + tig + 4) * BPAD + c]);
            }
#pragma unroll
            for (int mt = 0; mt < 4; mt++)
#pragma unroll
                for (int nt = 0; nt < 8; nt++)
                    mma_tf32(acc[mt][nt], a[mt], b[nt]);
        }
        __syncthreads();
    }

    // ---- epilogue ----
#pragma unroll
    for (int mt = 0; mt < 4; mt++) {
        const int r0 = row0 + wm * 64 + mt * 16 + group;
        const int r1 = r0 + 8;
        const float bia0 = (r0 < Msplit) ? bias0[r0] : bias1[r0 - Msplit];
        const float bia1 = (r1 < Msplit) ? bias0[r1] : bias1[r1 - Msplit];
        float s0 = 0.f, q0a = 0.f, s1 = 0.f, q1a = 0.f;
#pragma unroll
        for (int nt = 0; nt < 8; nt++) {
            const int n = col0 + wn * 64 + nt * 8 + tig * 2;
            const size_t i0 = ((size_t)bz * M + r0) * HW + n;
            const size_t i1 = ((size_t)bz * M + r1) * HW + n;
            const float4 c = acc[mt][nt];
            if (MODE == 0) {
                *(float2*)(Y + i0) = make_float2(c.x + bia0, c.y + bia0);
                *(float2*)(Y + i1) = make_float2(c.z + bia1, c.w + bia1);
            } else {
                const float2 f0 = *(const float2*)(fs + i0);
                const float2 f1 = *(const float2*)(fs + i1);
                const float2 q0 = *(const float2*)(o2 + i0);
                const float2 q1 = *(const float2*)(o2 + i1);
                float v; float2 r;
                v = c.x + bia0; r.x = f0.x + q0.x / (1.f + __expf(-v));
                v = c.y + bia0; r.y = f0.y + q0.y / (1.f + __expf(-v));
                *(float2*)(Y + i0) = r;
                s0 += r.x + r.y; q0a += r.x * r.x + r.y * r.y;
                v = c.z + bia1; r.x = f1.x + q1.x / (1.f + __expf(-v));
                v = c.w + bia1; r.y = f1.y + q1.y / (1.f + __expf(-v));
                *(float2*)(Y + i1) = r;
                s1 += r.x + r.y; q1a += r.x * r.x + r.y * r.y;
            }
        }
        if (MODE == 1) {
#pragma unroll
            for (int off = 1; off < 4; off <<= 1) {
                s0 += __shfl_xor_sync(0xffffffffu, s0, off);
                q0a += __shfl_xor_sync(0xffffffffu, q0a, off);
                s1 += __shfl_xor_sync(0xffffffffu, s1, off);
                q1a += __shfl_xor_sync(0xffffffffu, q1a, off);
            }
            if (tig == 0) {
                atomicAdd(&g_psum[bz * CN + r0], s0);
                atomicAdd(&g_psq[bz * CN + r0], q0a);
                atomicAdd(&g_psum[bz * CN + r1], s1);
                atomicAdd(&g_psq[bz * CN + r1], q1a);
            }
        }
    }
}

// ===========================================================================
// Epipolar attention: cp.async loads (raw fp32 -> HW tf32 truncation),
// 256-thread softmax (2 threads/column), 8-warp GEMM2. One block per (h,n,b).
// ===========================================================================
constexpr int SP = 136;
constexpr int ATT_SMEM = (2 * HDIM + WW) * SP * 4 + 2048;  // 176,128 B

__global__ __launch_bounds__(256, 1)
void attn_k(const float* __restrict__ q, const float* __restrict__ kv,
            float* __restrict__ ao)
{
    extern __shared__ float sm[];
    float* Qs = sm;                     // [96][136]
    float* Ks = sm + HDIM * SP;         // [96][136]  K, then V
    float* Ss = sm + 2 * HDIM * SP;     // [128][136] S[wp][w]
    float* red = sm + (2 * HDIM + WW) * SP;  // 512 floats
    const int h = blockIdx.x, n = blockIdx.y, b = blockIdx.z;
    const int tid = threadIdx.x;
    const int lane = tid & 31;
    const int warp = tid >> 5;
    const int group = lane >> 2;
    const int tig = lane & 3;

    const size_t qbase = (((size_t)b * CN + n * HDIM) * HH + h) * WW;
    const size_t kbase = (((size_t)b * 2 * CN + n * HDIM) * HH + h) * WW;
    const size_t vbase = kbase + (size_t)CN * HW;

    const uint32_t sQ = smem_u32(Qs), sK = smem_u32(Ks);

    // ---- Q, K loads via cp.async: 96 rows x 32 chunks(16B) = 3072 chunks each ----
#pragma unroll
    for (int i = 0; i < 12; i++) {
        const int ch = tid + i * 256;
        const int row = ch >> 5;          // 32 chunks per row
        const int c4 = (ch & 31) * 4;     // float offset 0..124
        cp16(sQ + (row * SP + c4) * 4, q + qbase + (size_t)row * HW + c4);
        cp16(sK + (row * SP + c4) * 4, kv + kbase + (size_t)row * HW + c4);
    }
    asm volatile("cp.async.commit_group;" ::: "memory");
    asm volatile("cp.async.wait_group 0;" ::: "memory");
    __syncthreads();

    {   // GEMM1: S[wp][w] = scale * sum_cc K[cc][wp] * Q[cc][w]  (8 warps, 64x32)
        const int wm = warp & 1, wn = warp >> 1;
        float4 acc[4][4];
#pragma unroll
        for (int i = 0; i < 4; i++)
#pragma unroll
            for (int j = 0; j < 4; j++) acc[i][j] = make_float4(0.f, 0.f, 0.f, 0.f);
#pragma unroll
        for (int kk = 0; kk < HDIM; kk += 8) {
            uint32_t a[4][4], bfr[4][2];
#pragma unroll
            for (int mt = 0; mt < 4; mt++) {
                const int wp = wm * 64 + mt * 16 + group;
                a[mt][0] = __float_as_uint(Ks[(kk + tig) * SP + wp]);
                a[mt][1] = __float_as_uint(Ks[(kk + tig) * SP + wp + 8]);
                a[mt][2] = __float_as_uint(Ks[(kk + tig + 4) * SP + wp]);
                a[mt][3] = __float_as_uint(Ks[(kk + tig + 4) * SP + wp + 8]);
            }
#pragma unroll
            for (int nt = 0; nt < 4; nt++) {
                const int w = wn * 32 + nt * 8 + group;
                bfr[nt][0] = __float_as_uint(Qs[(kk + tig) * SP + w]);
                bfr[nt][1] = __float_as_uint(Qs[(kk + tig + 4) * SP + w]);
            }
#pragma unroll
            for (int mt = 0; mt < 4; mt++)
#pragma unroll
                for (int nt = 0; nt < 4; nt++)
                    mma_tf32(acc[mt][nt], a[mt], bfr[nt]);
        }
        const float scale = 0.10206207261596575f;  // 1/sqrt(96)
#pragma unroll
        for (int mt = 0; mt < 4; mt++) {
            const int wp = wm * 64 + mt * 16 + group;
#pragma unroll
            for (int nt = 0; nt < 4; nt++) {
                const int w = wn * 32 + nt * 8 + tig * 2;
                const float4 c = acc[mt][nt];
                *(float2*)&Ss[wp * SP + w] = make_float2(c.x * scale, c.y * scale);
                *(float2*)&Ss[(wp + 8) * SP + w] = make_float2(c.z * scale, c.w * scale);
            }
        }
    }
    __syncthreads();

    // ---- V prefetch (into Ks) while softmax runs: 3072 chunks ----
#pragma unroll
    for (int i = 0; i < 12; i++) {
        const int ch = tid + i * 256;
        const int row = ch >> 5;
        const int c4 = (ch & 31) * 4;
        cp16(sK + (row * SP + c4) * 4, kv + vbase + (size_t)row * HW + c4);
    }
    asm volatile("cp.async.commit_group;" ::: "memory");

    {   // softmax: 2 threads per column (halves of wp)
        const int w = tid & 127;
        const int hs = tid >> 7;
        const int wp0 = hs * 64;
        float mx = -1e30f;
#pragma unroll 8
        for (int i = 0; i < 64; i++) mx = fmaxf(mx, Ss[(wp0 + i) * SP + w]);
        red[hs * 128 + w] = mx;
        __syncthreads();
        const float gm = fmaxf(red[w], red[128 + w]);
        float s = 0.f;
#pragma unroll 8
        for (int i = 0; i < 64; i++) {
            const float e = __expf(Ss[(wp0 + i) * SP + w] - gm);
            Ss[(wp0 + i) * SP + w] = e;
            s += e;
        }
        red[256 + hs * 128 + w] = s;
        __syncthreads();
        const float inv = 1.f / (red[256 + w] + red[384 + w]);
#pragma unroll 8
        for (int i = 0; i < 64; i++) Ss[(wp0 + i) * SP + w] *= inv;
    }
    asm volatile("cp.async.wait_group 0;" ::: "memory");
    __syncthreads();

    {   // GEMM2: out[cc][w] = sum_wp V[cc][wp] * P[wp][w]; 8 warps, 96x16 each
        const int c0 = warp * 16;
        float4 acc[6][2];
#pragma unroll
        for (int mt = 0; mt < 6; mt++)
#pragma unroll
            for (int nt = 0; nt < 2; nt++) acc[mt][nt] = make_float4(0.f, 0.f, 0.f, 0.f);
#pragma unroll 4
        for (int kk = 0; kk < WW; kk += 8) {
            uint32_t a[6][4], bfr[2][2];
#pragma unroll
            for (int mt = 0; mt < 6; mt++) {
                const int r = mt * 16 + group;
                a[mt][0] = __float_as_uint(Ks[r * SP + kk + tig]);
                a[mt][1] = __float_as_uint(Ks[(r + 8) * SP + kk + tig]);
                a[mt][2] = __float_as_uint(Ks[r * SP + kk + tig + 4]);
                a[mt][3] = __float_as_uint(Ks[(r + 8) * SP + kk + tig + 4]);
            }
#pragma unroll
            for (int nt = 0; nt < 2; nt++) {
                const int c = c0 + nt * 8 + group;
                bfr[nt][0] = __float_as_uint(Ss[(kk + tig) * SP + c]);
                bfr[nt][1] = __float_as_uint(Ss[(kk + tig + 4) * SP + c]);
            }
#pragma unroll
            for (int mt = 0; mt < 6; mt++)
#pragma unroll
                for (int nt = 0; nt < 2; nt++)
                    mma_tf32(acc[mt][nt], a[mt], bfr[nt]);
        }
#pragma unroll
        for (int mt = 0; mt < 6; mt++) {
            const int r = mt * 16 + group;
#pragma unroll
            for (int nt = 0; nt < 2; nt++) {
                const int w = c0 + nt * 8 + tig * 2;
                const float4 c = acc[mt][nt];
                *(float2*)(ao + qbase + (size_t)r * HW + w) = make_float2(c.x, c.y);
                *(float2*)(ao + qbase + (size_t)(r + 8) * HW + w) = make_float2(c.z, c.w);
            }
        }
    }
}

// ===========================================================================
// BatchNorm finalize + apply (stats fused into gate GEMM epilogue)
// ===========================================================================
__global__ void bnfin_k(const float* __restrict__ gamma,
                        const float* __restrict__ beta)
{
    const int c = threadIdx.x;
    float s = 0.f, sq = 0.f;
#pragma unroll
    for (int b = 0; b < BB; b++) { s += g_psum[b * CN + c]; sq += g_psq[b * CN + c]; }
    const float invN = 1.f / (float)(BB * HW);
    const float mean = s * invN;
    const float var = sq * invN - mean * mean;
    const float inv = rsqrtf(var + 1e-5f);
    const float sc = gamma[c] * inv;
    g_scale[c] = sc;
    g_shift[c] = beta[c] - mean * sc;
}

__global__ void bnapply_k(float* __restrict__ y)
{
    const size_t i = ((size_t)blockIdx.x * 256 + threadIdx.x) * 4;
    const int c = (int)((i >> 13) % CN);
    float4 v = *(float4*)(y + i);
    const float sc = g_scale[c], sh = g_shift[c];
    v.x = v.x * sc + sh;
    v.y = v.y * sc + sh;
    v.z = v.z * sc + sh;
    v.w = v.w * sc + sh;
    *(float4*)(y + i) = v;
}

// ===========================================================================
extern "C" void kernel_launch(void* const* d_in, const int* in_sizes, int n_in,
                              void* d_out, int out_size)
{
    (void)in_sizes; (void)n_in; (void)out_size;
    const float* fs    = (const float*)d_in[0];
    const float* fo    = (const float*)d_in[1];
    const float* wq    = (const float*)d_in[2];
    const float* bq    = (const float*)d_in[3];
    const float* wk    = (const float*)d_in[4];
    const float* bk    = (const float*)d_in[5];
    const float* wv    = (const float*)d_in[6];
    const float* bv    = (const float*)d_in[7];
    const float* wo    = (const float*)d_in[8];
    const float* bo    = (const float*)d_in[9];
    const float* wg    = (const float*)d_in[10];
    const float* bg    = (const float*)d_in[11];
    const float* gamma = (const float*)d_in[12];
    const float* beta  = (const float*)d_in[13];
    float* out = (float*)d_out;

    float *q, *kvb, *ao, *o2, *psum, *psq;
    cudaGetSymbolAddress((void**)&q,    g_q);
    cudaGetSymbolAddress((void**)&kvb,  g_kv);
    cudaGetSymbolAddress((void**)&ao,   g_ao);
    cudaGetSymbolAddress((void**)&o2,   g_o2);
    cudaGetSymbolAddress((void**)&psum, g_psum);
    cudaGetSymbolAddress((void**)&psq,  g_psq);

    cudaFuncSetAttribute(gemm_t<0>, cudaFuncAttributeMaxDynamicSharedMemorySize, GSMEM);
    cudaFuncSetAttribute(gemm_t<1>, cudaFuncAttributeMaxDynamicSharedMemorySize, GSMEM);
    cudaFuncSetAttribute(attn_k, cudaFuncAttributeMaxDynamicSharedMemorySize, ATT_SMEM);

    // zero fused-BN accumulators (graph-capturable async memsets)
    cudaMemsetAsync(psum, 0, BB * CN * sizeof(float));
    cudaMemsetAsync(psq,  0, BB * CN * sizeof(float));

    const dim3 blk(256);
    gemm_t<0><<<dim3(32, 3, 8), blk, GSMEM>>>(wq, wq, CN, CN, bq, bq,
                                              fs, fs, CN, CN, CN, q, nullptr, nullptr);
    gemm_t<0><<<dim3(32, 6, 8), blk, GSMEM>>>(wk, wv, CN, CN, bk, bv,
                                              fo, fo, CN, 2 * CN, CN, kvb, nullptr, nullptr);
    attn_k<<<dim3(HH, NHEAD, BB), blk, ATT_SMEM>>>(q, kvb, ao);
    gemm_t<0><<<dim3(32, 3, 8), blk, GSMEM>>>(wo, wo, CN, CN, bo, bo,
                                              ao, ao, CN, CN, CN, o2, nullptr, nullptr);
    gemm_t<1><<<dim3(32, 3, 8), blk, GSMEM>>>(wg, wg, CN, 2 * CN, bg, bg,
                                              fs, o2, CN, CN, 2 * CN, out, fs, o2);
    bnfin_k<<<1, CN>>>(gamma, beta);
    bnapply_k<<<BB * CN * HW / 1024, 256>>>(out);
}

// round 11
// speedup vs baseline: 1.2535x; 1.1440x over previous
#include <cuda_runtime.h>
#include <cstdint>

constexpr int CN = 384;
constexpr int NHEAD = 4;
constexpr int HDIM = 96;
constexpr int HH = 64;
constexpr int WW = 128;
constexpr int HW = HH * WW;   // 8192
constexpr int BB = 8;

// Scratch (device globals: allocation-free, harness-legal)
__device__ float g_q[BB * CN * HW];
__device__ float g_kv[BB * 2 * CN * HW];
__device__ float g_ao[BB * CN * HW];
__device__ float g_o2[BB * CN * HW];
__device__ float g_psum[BB * CN];
__device__ float g_psq[BB * CN];
__device__ float g_scale[CN];
__device__ float g_shift[CN];

__device__ __forceinline__ float to_tf32(float x) {
    uint32_t u;
    asm("cvt.rna.tf32.f32 %0, %1;" : "=r"(u) : "f"(x));
    return __uint_as_float(u);
}
__device__ __forceinline__ void mma_tf32(float4& d, const uint32_t a[4], const uint32_t b[2]) {
    asm volatile(
        "mma.sync.aligned.m16n8k8.row.col.f32.tf32.tf32.f32 "
        "{%0,%1,%2,%3}, {%4,%5,%6,%7}, {%8,%9}, {%0,%1,%2,%3};\n"
        : "+f"(d.x), "+f"(d.y), "+f"(d.z), "+f"(d.w)
        : "r"(a[0]), "r"(a[1]), "r"(a[2]), "r"(a[3]), "r"(b[0]), "r"(b[1]));
}
__device__ __forceinline__ uint32_t smem_u32(const void* p) {
    uint32_t a;
    asm("{ .reg .u64 t; cvta.to.shared.u64 t, %1; cvt.u32.u64 %0, t; }" : "=r"(a) : "l"(p));
    return a;
}
__device__ __forceinline__ void cp16(uint32_t d, const void* g) {
    asm volatile("cp.async.cg.shared.global [%0], [%1], 16;" :: "r"(d), "l"(g));
}

// ===========================================================================
// Projection GEMM — EXACT R3 mainloop (best measured: 163.6us/unit).
// tf32 mma, block 128(M) x 256(N), K-tile 16, 8 warps at 64x64,
// register-prefetch double buffer. MODE 0: plain store.
// MODE 1: gate epilogue + fused BN-stats accumulation.
// ===========================================================================
constexpr int APAD = 20;
constexpr int BPAD = 264;
constexpr int ASZ = 128 * APAD;
constexpr int BSZ = 16 * BPAD;
constexpr int GSMEM = (2 * ASZ + 2 * BSZ) * 4;   // 54,272 B

template <int MODE>
__global__ __launch_bounds__(256, 1)
void gemm_t(const float* __restrict__ A0, const float* __restrict__ A1,
            int Msplit, int lda,
            const float* __restrict__ bias0, const float* __restrict__ bias1,
            const float* __restrict__ X0, const float* __restrict__ X1,
            int Ksplit, int M, int K,
            float* __restrict__ Y,
            const float* __restrict__ fs, const float* __restrict__ o2)
{
    extern __shared__ float smg[];
    float* Asb = smg;
    float* Bsb = smg + 2 * ASZ;

    const int tid = threadIdx.x;
    const int lane = tid & 31;
    const int warp = tid >> 5;
    const int group = lane >> 2;
    const int tig = lane & 3;
    const int wm = warp & 1;
    const int wn = warp >> 1;
    const int row0 = blockIdx.y * 128;
    const int col0 = blockIdx.x * 256;
    const int bz = blockIdx.z;
    const int C1 = K - Ksplit;

    const int m_ld = tid >> 1;
    const int kq = (tid & 1) * 8;
    const int mg = row0 + m_ld;
    const float* aptr = (mg < Msplit) ? (A0 + (size_t)mg * lda)
                                      : (A1 + (size_t)(mg - Msplit) * lda);
    const int kb = tid >> 5;
    const int nq = lane * 4;

    float4 acc[4][8];
#pragma unroll
    for (int i = 0; i < 4; i++)
#pragma unroll
        for (int j = 0; j < 8; j++) acc[i][j] = make_float4(0.f, 0.f, 0.f, 0.f);

    const int iters = K >> 4;

    auto xrow = [&](int cg) -> const float* {
        return (cg < Ksplit) ? (X0 + ((size_t)bz * Ksplit + cg) * HW)
                             : (X1 + ((size_t)bz * C1 + (cg - Ksplit)) * HW);
    };

    // ---- prologue: load tile 0 into buffer 0 (B: 8 warps x 2 k-rows x 32 lanes x 4) ----
    {
        float4 a0 = *(const float4*)(aptr + kq);
        float4 a1 = *(const float4*)(aptr + kq + 4);
        *(float4*)&Asb[m_ld * APAD + kq] =
            make_float4(to_tf32(a0.x), to_tf32(a0.y), to_tf32(a0.z), to_tf32(a0.w));
        *(float4*)&Asb[m_ld * APAD + kq + 4] =
            make_float4(to_tf32(a1.x), to_tf32(a1.y), to_tf32(a1.z), to_tf32(a1.w));
#pragma unroll
        for (int j = 0; j < 2; j++) {
            const int kr = kb + 8 * j;
            const int nc = (j == 0) ? nq : (nq + 128);
            const int kr2 = kb;
            (void)kr2;
            float4 b = *(const float4*)(xrow(kb) + col0 + ((j == 0) ? nq : nq + 128));
            (void)kr; (void)b;
        }
        // B loader: each thread covers 2 half-rows: (kb, nq) and (kb+8, nq)
        {
            float4 b0 = *(const float4*)(xrow(kb) + col0 + nq);
            float4 b1 = *(const float4*)(xrow(kb) + col0 + nq + 128);
            *(float4*)&Bsb[kb * BPAD + nq] =
                make_float4(to_tf32(b0.x), to_tf32(b0.y), to_tf32(b0.z), to_tf32(b0.w));
            *(float4*)&Bsb[kb * BPAD + nq + 128] =
                make_float4(to_tf32(b1.x), to_tf32(b1.y), to_tf32(b1.z), to_tf32(b1.w));
            float4 b2 = *(const float4*)(xrow(kb + 8) + col0 + nq);
            float4 b3 = *(const float4*)(xrow(kb + 8) + col0 + nq + 128);
            *(float4*)&Bsb[(kb + 8) * BPAD + nq] =
                make_float4(to_tf32(b2.x), to_tf32(b2.y), to_tf32(b2.z), to_tf32(b2.w));
            *(float4*)&Bsb[(kb + 8) * BPAD + nq + 128] =
                make_float4(to_tf32(b3.x), to_tf32(b3.y), to_tf32(b3.z), to_tf32(b3.w));
        }
    }
    __syncthreads();

    for (int it = 0; it < iters; it++) {
        const int buf = it & 1;
        float4 pa0, pa1, pb0, pb1, pb2, pb3;
        const bool more = (it + 1 < iters);
        if (more) {
            const int k0 = (it + 1) << 4;
            pa0 = *(const float4*)(aptr + k0 + kq);
            pa1 = *(const float4*)(aptr + k0 + kq + 4);
            pb0 = *(const float4*)(xrow(k0 + kb) + col0 + nq);
            pb1 = *(const float4*)(xrow(k0 + kb) + col0 + nq + 128);
            pb2 = *(const float4*)(xrow(k0 + kb + 8) + col0 + nq);
            pb3 = *(const float4*)(xrow(k0 + kb + 8) + col0 + nq + 128);
        }

        const float* Ab = Asb + buf * ASZ;
        const float* Bb = Bsb + buf * BSZ;
#pragma unroll
        for (int kk = 0; kk < 16; kk += 8) {
            uint32_t a[4][4], b[8][2];
#pragma unroll
            for (int mt = 0; mt < 4; mt++) {
                const int r = wm * 64 + mt * 16 + group;
                a[mt][0] = __float_as_uint(Ab[r * APAD + kk + tig]);
                a[mt][1] = __float_as_uint(Ab[(r + 8) * APAD + kk + tig]);
                a[mt][2] = __float_as_uint(Ab[r * APAD + kk + tig + 4]);
                a[mt][3] = __float_as_uint(Ab[(r + 8) * APAD + kk + tig + 4]);
            }
#pragma unroll
            for (int nt = 0; nt < 8; nt++) {
                const int c = wn * 64 + nt * 8 + group;
                b[nt][0] = __float_as_uint(Bb[(kk + tig) * BPAD + c]);
                b[nt][1] = __float_as_uint(Bb[(kk + tig + 4) * BPAD + c]);
            }
#pragma unroll
            for (int mt = 0; mt < 4; mt++)
#pragma unroll
                for (int nt = 0; nt < 8; nt++)
                    mma_tf32(acc[mt][nt], a[mt], b[nt]);
        }

        if (more) {
            float* An = Asb + (buf ^ 1) * ASZ;
            float* Bn = Bsb + (buf ^ 1) * BSZ;
            *(float4*)&An[m_ld * APAD + kq] =
                make_float4(to_tf32(pa0.x), to_tf32(pa0.y), to_tf32(pa0.z), to_tf32(pa0.w));
            *(float4*)&An[m_ld * APAD + kq + 4] =
                make_float4(to_tf32(pa1.x), to_tf32(pa1.y), to_tf32(pa1.z), to_tf32(pa1.w));
            *(float4*)&Bn[kb * BPAD + nq] =
                make_float4(to_tf32(pb0.x), to_tf32(pb0.y), to_tf32(pb0.z), to_tf32(pb0.w));
            *(float4*)&Bn[kb * BPAD + nq + 128] =
                make_float4(to_tf32(pb1.x), to_tf32(pb1.y), to_tf32(pb1.z), to_tf32(pb1.w));
            *(float4*)&Bn[(kb + 8) * BPAD + nq] =
                make_float4(to_tf32(pb2.x), to_tf32(pb2.y), to_tf32(pb2.z), to_tf32(pb2.w));
            *(float4*)&Bn[(kb + 8) * BPAD + nq + 128] =
                make_float4(to_tf32(pb3.x), to_tf32(pb3.y), to_tf32(pb3.z), to_tf32(pb3.w));
        }
        __syncthreads();
    }

    // ---- epilogue ----
#pragma unroll
    for (int mt = 0; mt < 4; mt++) {
        const int r0 = row0 + wm * 64 + mt * 16 + group;
        const int r1 = r0 + 8;
        const float bia0 = (r0 < Msplit) ? bias0[r0] : bias1[r0 - Msplit];
        const float bia1 = (r1 < Msplit) ? bias0[r1] : bias1[r1 - Msplit];
        float s0 = 0.f, q0a = 0.f, s1 = 0.f, q1a = 0.f;
#pragma unroll
        for (int nt = 0; nt < 8; nt++) {
            const int n = col0 + wn * 64 + nt * 8 + tig * 2;
            const size_t i0 = ((size_t)bz * M + r0) * HW + n;
            const size_t i1 = ((size_t)bz * M + r1) * HW + n;
            const float4 c = acc[mt][nt];
            if (MODE == 0) {
                *(float2*)(Y + i0) = make_float2(c.x + bia0, c.y + bia0);
                *(float2*)(Y + i1) = make_float2(c.z + bia1, c.w + bia1);
            } else {
                const float2 f0 = *(const float2*)(fs + i0);
                const float2 f1 = *(const float2*)(fs + i1);
                const float2 q0 = *(const float2*)(o2 + i0);
                const float2 q1 = *(const float2*)(o2 + i1);
                float v; float2 r;
                v = c.x + bia0; r.x = f0.x + q0.x / (1.f + __expf(-v));
                v = c.y + bia0; r.y = f0.y + q0.y / (1.f + __expf(-v));
                *(float2*)(Y + i0) = r;
                s0 += r.x + r.y; q0a += r.x * r.x + r.y * r.y;
                v = c.z + bia1; r.x = f1.x + q1.x / (1.f + __expf(-v));
                v = c.w + bia1; r.y = f1.y + q1.y / (1.f + __expf(-v));
                *(float2*)(Y + i1) = r;
                s1 += r.x + r.y; q1a += r.x * r.x + r.y * r.y;
            }
        }
        if (MODE == 1) {
#pragma unroll
            for (int off = 1; off < 4; off <<= 1) {
                s0 += __shfl_xor_sync(0xffffffffu, s0, off);
                q0a += __shfl_xor_sync(0xffffffffu, q0a, off);
                s1 += __shfl_xor_sync(0xffffffffu, s1, off);
                q1a += __shfl_xor_sync(0xffffffffu, q1a, off);
            }
            if (tig == 0) {
                atomicAdd(&g_psum[bz * CN + r0], s0);
                atomicAdd(&g_psq[bz * CN + r0], q0a);
                atomicAdd(&g_psum[bz * CN + r1], s1);
                atomicAdd(&g_psq[bz * CN + r1], q1a);
            }
        }
    }
}

// ===========================================================================
// Epipolar attention (R10, loader-fixed): cp.async loads, 256-thread softmax,
// 8-warp GEMM2. One block per (h, n, b).
// ===========================================================================
constexpr int SP = 136;
constexpr int ATT_SMEM = (2 * HDIM + WW) * SP * 4 + 2048;  // 176,128 B

__global__ __launch_bounds__(256, 1)
void attn_k(const float* __restrict__ q, const float* __restrict__ kv,
            float* __restrict__ ao)
{
    extern __shared__ float sm[];
    float* Qs = sm;                     // [96][136]
    float* Ks = sm + HDIM * SP;         // [96][136]  K, then V
    float* Ss = sm + 2 * HDIM * SP;     // [128][136] S[wp][w]
    float* red = sm + (2 * HDIM + WW) * SP;  // 512 floats
    const int h = blockIdx.x, n = blockIdx.y, b = blockIdx.z;
    const int tid = threadIdx.x;
    const int lane = tid & 31;
    const int warp = tid >> 5;
    const int group = lane >> 2;
    const int tig = lane & 3;

    const size_t qbase = (((size_t)b * CN + n * HDIM) * HH + h) * WW;
    const size_t kbase = (((size_t)b * 2 * CN + n * HDIM) * HH + h) * WW;
    const size_t vbase = kbase + (size_t)CN * HW;

    const uint32_t sQ = smem_u32(Qs), sK = smem_u32(Ks);

    // ---- Q, K loads via cp.async: 96 rows x 32 chunks(16B) each ----
#pragma unroll
    for (int i = 0; i < 12; i++) {
        const int ch = tid + i * 256;
        const int row = ch >> 5;
        const int c4 = (ch & 31) * 4;
        cp16(sQ + (row * SP + c4) * 4, q + qbase + (size_t)row * HW + c4);
        cp16(sK + (row * SP + c4) * 4, kv + kbase + (size_t)row * HW + c4);
    }
    asm volatile("cp.async.commit_group;" ::: "memory");
    asm volatile("cp.async.wait_group 0;" ::: "memory");
    __syncthreads();

    {   // GEMM1: S[wp][w] = scale * sum_cc K[cc][wp] * Q[cc][w]  (8 warps, 64x32)
        const int wm = warp & 1, wn = warp >> 1;
        float4 acc[4][4];
#pragma unroll
        for (int i = 0; i < 4; i++)
#pragma unroll
            for (int j = 0; j < 4; j++) acc[i][j] = make_float4(0.f, 0.f, 0.f, 0.f);
#pragma unroll
        for (int kk = 0; kk < HDIM; kk += 8) {
            uint32_t a[4][4], bfr[4][2];
#pragma unroll
            for (int mt = 0; mt < 4; mt++) {
                const int wp = wm * 64 + mt * 16 + group;
                a[mt][0] = __float_as_uint(Ks[(kk + tig) * SP + wp]);
                a[mt][1] = __float_as_uint(Ks[(kk + tig) * SP + wp + 8]);
                a[mt][2] = __float_as_uint(Ks[(kk + tig + 4) * SP + wp]);
                a[mt][3] = __float_as_uint(Ks[(kk + tig + 4) * SP + wp + 8]);
            }
#pragma unroll
            for (int nt = 0; nt < 4; nt++) {
                const int w = wn * 32 + nt * 8 + group;
                bfr[nt][0] = __float_as_uint(Qs[(kk + tig) * SP + w]);
                bfr[nt][1] = __float_as_uint(Qs[(kk + tig + 4) * SP + w]);
            }
#pragma unroll
            for (int mt = 0; mt < 4; mt++)
#pragma unroll
                for (int nt = 0; nt < 4; nt++)
                    mma_tf32(acc[mt][nt], a[mt], bfr[nt]);
        }
        const float scale = 0.10206207261596575f;  // 1/sqrt(96)
#pragma unroll
        for (int mt = 0; mt < 4; mt++) {
            const int wp = wm * 64 + mt * 16 + group;
#pragma unroll
            for (int nt = 0; nt < 4; nt++) {
                const int w = wn * 32 + nt * 8 + tig * 2;
                const float4 c = acc[mt][nt];
                *(float2*)&Ss[wp * SP + w] = make_float2(c.x * scale, c.y * scale);
                *(float2*)&Ss[(wp + 8) * SP + w] = make_float2(c.z * scale, c.w * scale);
            }
        }
    }
    __syncthreads();

    // ---- V prefetch (into Ks) while softmax runs ----
#pragma unroll
    for (int i = 0; i < 12; i++) {
        const int ch = tid + i * 256;
        const int row = ch >> 5;
        const int c4 = (ch & 31) * 4;
        cp16(sK + (row * SP + c4) * 4, kv + vbase + (size_t)row * HW + c4);
    }
    asm volatile("cp.async.commit_group;" ::: "memory");

    {   // softmax: 2 threads per column
        const int w = tid & 127;
        const int hs = tid >> 7;
        const int wp0 = hs * 64;
        float mx = -1e30f;
#pragma unroll 8
        for (int i = 0; i < 64; i++) mx = fmaxf(mx, Ss[(wp0 + i) * SP + w]);
        red[hs * 128 + w] = mx;
        __syncthreads();
        const float gm = fmaxf(red[w], red[128 + w]);
        float s = 0.f;
#pragma unroll 8
        for (int i = 0; i < 64; i++) {
            const float e = __expf(Ss[(wp0 + i) * SP + w] - gm);
            Ss[(wp0 + i) * SP + w] = e;
            s += e;
        }
        red[256 + hs * 128 + w] = s;
        __syncthreads();
        const float inv = 1.f / (red[256 + w] + red[384 + w]);
#pragma unroll 8
        for (int i = 0; i < 64; i++) Ss[(wp0 + i) * SP + w] *= inv;
    }
    asm volatile("cp.async.wait_group 0;" ::: "memory");
    __syncthreads();

    {   // GEMM2: out[cc][w] = sum_wp V[cc][wp] * P[wp][w]; 8 warps, 96x16 each
        const int c0 = warp * 16;
        float4 acc[6][2];
#pragma unroll
        for (int mt = 0; mt < 6; mt++)
#pragma unroll
            for (int nt = 0; nt < 2; nt++) acc[mt][nt] = make_float4(0.f, 0.f, 0.f, 0.f);
#pragma unroll 4
        for (int kk = 0; kk < WW; kk += 8) {
            uint32_t a[6][4], bfr[2][2];
#pragma unroll
            for (int mt = 0; mt < 6; mt++) {
                const int r = mt * 16 + group;
                a[mt][0] = __float_as_uint(Ks[r * SP + kk + tig]);
                a[mt][1] = __float_as_uint(Ks[(r + 8) * SP + kk + tig]);
                a[mt][2] = __float_as_uint(Ks[r * SP + kk + tig + 4]);
                a[mt][3] = __float_as_uint(Ks[(r + 8) * SP + kk + tig + 4]);
            }
#pragma unroll
            for (int nt = 0; nt < 2; nt++) {
                const int c = c0 + nt * 8 + group;
                bfr[nt][0] = __float_as_uint(Ss[(kk + tig) * SP + c]);
                bfr[nt][1] = __float_as_uint(Ss[(kk + tig + 4) * SP + c]);
            }
#pragma unroll
            for (int mt = 0; mt < 6; mt++)
#pragma unroll
                for (int nt = 0; nt < 2; nt++)
                    mma_tf32(acc[mt][nt], a[mt], bfr[nt]);
        }
#pragma unroll
        for (int mt = 0; mt < 6; mt++) {
            const int r = mt * 16 + group;
#pragma unroll
            for (int nt = 0; nt < 2; nt++) {
                const int w = c0 + nt * 8 + tig * 2;
                const float4 c = acc[mt][nt];
                *(float2*)(ao + qbase + (size_t)r * HW + w) = make_float2(c.x, c.y);
                *(float2*)(ao + qbase + (size_t)(r + 8) * HW + w) = make_float2(c.z, c.w);
            }
        }
    }
}

// ===========================================================================
// BatchNorm finalize + apply (stats fused into gate GEMM epilogue)
// ===========================================================================
__global__ void bnfin_k(const float* __restrict__ gamma,
                        const float* __restrict__ beta)
{
    const int c = threadIdx.x;
    float s = 0.f, sq = 0.f;
#pragma unroll
    for (int b = 0; b < BB; b++) { s += g_psum[b * CN + c]; sq += g_psq[b * CN + c]; }
    const float invN = 1.f / (float)(BB * HW);
    const float mean = s * invN;
    const float var = sq * invN - mean * mean;
    const float inv = rsqrtf(var + 1e-5f);
    const float sc = gamma[c] * inv;
    g_scale[c] = sc;
    g_shift[c] = beta[c] - mean * sc;
}

__global__ void bnapply_k(float* __restrict__ y)
{
    const size_t i = ((size_t)blockIdx.x * 256 + threadIdx.x) * 4;
    const int c = (int)((i >> 13) % CN);
    float4 v = *(float4*)(y + i);
    const float sc = g_scale[c], sh = g_shift[c];
    v.x = v.x * sc + sh;
    v.y = v.y * sc + sh;
    v.z = v.z * sc + sh;
    v.w = v.w * sc + sh;
    *(float4*)(y + i) = v;
}

// ===========================================================================
extern "C" void kernel_launch(void* const* d_in, const int* in_sizes, int n_in,
                              void* d_out, int out_size)
{
    (void)in_sizes; (void)n_in; (void)out_size;
    const float* fs    = (const float*)d_in[0];
    const float* fo    = (const float*)d_in[1];
    const float* wq    = (const float*)d_in[2];
    const float* bq    = (const float*)d_in[3];
    const float* wk    = (const float*)d_in[4];
    const float* bk    = (const float*)d_in[5];
    const float* wv    = (const float*)d_in[6];
    const float* bv    = (const float*)d_in[7];
    const float* wo    = (const float*)d_in[8];
    const float* bo    = (const float*)d_in[9];
    const float* wg    = (const float*)d_in[10];
    const float* bg    = (const float*)d_in[11];
    const float* gamma = (const float*)d_in[12];
    const float* beta  = (const float*)d_in[13];
    float* out = (float*)d_out;

    float *q, *kvb, *ao, *o2, *psum, *psq;
    cudaGetSymbolAddress((void**)&q,    g_q);
    cudaGetSymbolAddress((void**)&kvb,  g_kv);
    cudaGetSymbolAddress((void**)&ao,   g_ao);
    cudaGetSymbolAddress((void**)&o2,   g_o2);
    cudaGetSymbolAddress((void**)&psum, g_psum);
    cudaGetSymbolAddress((void**)&psq,  g_psq);

    cudaFuncSetAttribute(gemm_t<0>, cudaFuncAttributeMaxDynamicSharedMemorySize, GSMEM);
    cudaFuncSetAttribute(gemm_t<1>, cudaFuncAttributeMaxDynamicSharedMemorySize, GSMEM);
    cudaFuncSetAttribute(attn_k, cudaFuncAttributeMaxDynamicSharedMemorySize, ATT_SMEM);

    // zero fused-BN accumulators (graph-capturable async memsets)
    cudaMemsetAsync(psum, 0, BB * CN * sizeof(float));
    cudaMemsetAsync(psq,  0, BB * CN * sizeof(float));

    const dim3 blk(256);
    gemm_t<0><<<dim3(32, 3, 8), blk, GSMEM>>>(wq, wq, CN, CN, bq, bq,
                                              fs, fs, CN, CN, CN, q, nullptr, nullptr);
    gemm_t<0><<<dim3(32, 6, 8), blk, GSMEM>>>(wk, wv, CN, CN, bk, bv,
                                              fo, fo, CN, 2 * CN, CN, kvb, nullptr, nullptr);
    attn_k<<<dim3(HH, NHEAD, BB), blk, ATT_SMEM>>>(q, kvb, ao);
    gemm_t<0><<<dim3(32, 3, 8), blk, GSMEM>>>(wo, wo, CN, CN, bo, bo,
                                              ao, ao, CN, CN, CN, o2, nullptr, nullptr);
    gemm_t<1><<<dim3(32, 3, 8), blk, GSMEM>>>(wg, wg, CN, 2 * CN, bg, bg,
                                              fs, o2, CN, CN, 2 * CN, out, fs, o2);
    bnfin_k<<<1, CN>>>(gamma, beta);
    bnapply_k<<<BB * CN * HW / 1024, 256>>>(out);
}